// round 16
// baseline (speedup 1.0000x reference)
#include <cuda_runtime.h>
#include <cuda_fp16.h>
#include <cstdint>

// DSAttention flash attention, all-fp16 MMA (fp32 accum), software-pipelined:
// iteration body = softmax(kt) | barrier | prefetch(kt+2) | {QK(kt+1) ∥ PV(kt)}.
// The two MMA chains are register-independent -> ptxas interleaves them,
// hiding MMA/LDS latency that the serial QK->softmax->PV order exposed.
// K/D prefetch distance 2, V distance 1; 2x2 buffers, one barrier per tile.

#define LQ 2048
#define HH 8
#define BM 64
#define BN 64
#define ED 64
#define NTHREADS 128
#define KVSH 72                  // halves per row (144 B)
#define KVB  (64 * KVSH * 2)     // 9216 B per tile buffer
#define QSTR 68                  // floats per Q-stage row

#define OFFB_K0 0
#define OFFB_K1 (KVB)
#define OFFB_V0 (2 * KVB)
#define OFFB_V1 (3 * KVB)
#define OFFB_D0 (4 * KVB)
#define OFFB_D1 (4 * KVB + 256)
#define OFFB_Q  (4 * KVB + 512)
#define SMEM_BYTES (OFFB_Q + 64 * QSTR * 4)   // 54784 B -> 3 CTAs/SM

__device__ __half g_Kh[2 * 8 * 2048 * 64];    // 4 MB: fp16 K, e-interleaved
__device__ __half g_Vth[2 * 8 * 64 * 2048];   // 4 MB: fp16 V, [bh][e][s] interleaved

__device__ __forceinline__ uint32_t pack_h2(float a, float b) {
    __half2 h = __floats2half2_rn(a, b);
    return *(uint32_t*)&h;
}
__device__ __forceinline__ void cpasync16(uint32_t dst, const void* src) {
    asm volatile("cp.async.cg.shared.global [%0], [%1], 16;" :: "r"(dst), "l"(src));
}
__device__ __forceinline__ void cp_commit() {
    asm volatile("cp.async.commit_group;" ::: "memory");
}
__device__ __forceinline__ void cp_wait0() {
    asm volatile("cp.async.wait_group 0;" ::: "memory");
}
__device__ __forceinline__ void cp_wait1() {
    asm volatile("cp.async.wait_group 1;" ::: "memory");
}
__device__ __forceinline__ void mma_f16(float* d, const uint32_t* a,
                                        uint32_t b0, uint32_t b1) {
    asm volatile(
        "mma.sync.aligned.m16n8k16.row.col.f32.f16.f16.f32 "
        "{%0,%1,%2,%3}, {%4,%5,%6,%7}, {%8,%9}, {%0,%1,%2,%3};"
        : "+f"(d[0]), "+f"(d[1]), "+f"(d[2]), "+f"(d[3])
        : "r"(a[0]), "r"(a[1]), "r"(a[2]), "r"(a[3]), "r"(b0), "r"(b1));
}

// perm within a 16-group: physical p holds logical 2*(p>>2) + (p&1) + 8*((p>>1)&1)
__device__ __forceinline__ int perm16(int p) {
    return 2 * (p >> 2) + (p & 1) + 8 * ((p >> 1) & 1);
}

// ---------------- prep (unchanged from R15) ----------------
__global__ __launch_bounds__(256)
void prep_kernel(const float* __restrict__ Kg, const float* __restrict__ Vg)
{
    const int stile = blockIdx.x;
    const int h     = blockIdx.y;
    const int b     = blockIdx.z;
    const int tid   = threadIdx.x;
    const int bh    = b * HH + h;
    const int s0    = stile * 64;

    __shared__ float tile[64][65];

    {
        int r   = tid >> 2;
        int grp = tid & 3;
        const float* src = Kg + ((size_t)(b * LQ + s0 + r) * HH + h) * ED + grp * 16;
        float f[16];
        *(float4*)(f)      = *(const float4*)(src);
        *(float4*)(f + 4)  = *(const float4*)(src + 4);
        *(float4*)(f + 8)  = *(const float4*)(src + 8);
        *(float4*)(f + 12) = *(const float4*)(src + 12);
        __half hh16[16];
        #pragma unroll
        for (int p = 0; p < 16; ++p) hh16[p] = __float2half_rn(f[perm16(p)]);
        __half* dst = g_Kh + ((size_t)bh * LQ + s0 + r) * ED + grp * 16;
        *(uint4*)(dst)     = *(uint4*)(hh16);
        *(uint4*)(dst + 8) = *(uint4*)(hh16 + 8);
    }

    const float* Vbh = Vg + ((size_t)(b * LQ) * HH + h) * ED;
    #pragma unroll
    for (int it = 0; it < 4; ++it) {
        int u  = tid + it * 256;
        int r  = u >> 4;
        int c4 = u & 15;
        float4 v = *(const float4*)(Vbh + (size_t)(s0 + r) * (HH * ED) + 4 * c4);
        tile[r][4 * c4 + 0] = v.x;
        tile[r][4 * c4 + 1] = v.y;
        tile[r][4 * c4 + 2] = v.z;
        tile[r][4 * c4 + 3] = v.w;
    }
    __syncthreads();
    {
        int e   = tid >> 2;
        int grp = tid & 3;
        __half hh16[16];
        #pragma unroll
        for (int p = 0; p < 16; ++p)
            hh16[p] = __float2half_rn(tile[grp * 16 + perm16(p)][e]);
        __half* dst = g_Vth + ((size_t)bh * ED + e) * LQ + s0 + grp * 16;
        *(uint4*)(dst)     = *(uint4*)(hh16);
        *(uint4*)(dst + 8) = *(uint4*)(hh16 + 8);
    }
}

// ---------------- main ----------------
__global__ __launch_bounds__(NTHREADS, 3)
void dsattn_tc(const float* __restrict__ Qg, const float* __restrict__ Taug,
               const float* __restrict__ Dg, float* __restrict__ Og)
{
    const float scale = 0.125f;

    const int mtile = (int)gridDim.x - 1 - (int)blockIdx.x;   // heavy first
    const int h     = blockIdx.y;
    const int b     = blockIdx.z;
    const int bh    = b * HH + h;

    const int tid  = threadIdx.x;
    const int wid  = tid >> 5;
    const int lane = tid & 31;
    const int g    = lane >> 2;
    const int t4   = lane & 3;

    extern __shared__ char smemc[];
    __half* sKh[2] = { (__half*)(smemc + OFFB_K0), (__half*)(smemc + OFFB_K1) };
    __half* sVh[2] = { (__half*)(smemc + OFFB_V0), (__half*)(smemc + OFFB_V1) };
    float*  sD [2] = { (float*)(smemc + OFFB_D0),  (float*)(smemc + OFFB_D1) };
    float*  sQ     = (float*)(smemc + OFFB_Q);

    const uint32_t su = (uint32_t)__cvta_generic_to_shared(smemc);
    const uint32_t sKu[2] = { su + OFFB_K0, su + OFFB_K1 };
    const uint32_t sVu[2] = { su + OFFB_V0, su + OFFB_V1 };
    const uint32_t sDu[2] = { su + OFFB_D0, su + OFFB_D1 };
    const uint32_t sQu    = su + OFFB_Q;

    const float ts = Taug[b] * scale;
    const int wrow = wid * 16;

    const float*  Qbase  = Qg + ((size_t)(b * LQ) * HH + h) * ED;
    const __half* Khbase = g_Kh + (size_t)bh * LQ * ED;
    const __half* Vtbase = g_Vth + (size_t)bh * ED * LQ;
    const float*  Dbase  = Dg + b * LQ;

    const int nkt = mtile + 1;
    const int rlo8 = tid >> 3, c8 = tid & 7;   // KV loader coords (128 B rows)

    const int row0 = mtile * BM + wrow + g;
    const int row1 = row0 + 8;

    // ---- prologue ----
    // group A: Q stage, K(0)->K[0], D(0)->D[0]
    {
        const int q0 = mtile * BM;
        const int r_lo = tid >> 4, c4 = tid & 15;
        #pragma unroll
        for (int it = 0; it < 8; ++it) {
            int r = r_lo + it * 8;
            cpasync16(sQu + (r * QSTR + c4 * 4) * 4,
                      Qbase + (size_t)(q0 + r) * (HH * ED) + c4 * 4);
        }
        #pragma unroll
        for (int it = 0; it < 4; ++it) {
            int r = rlo8 + it * 16;
            cpasync16(sKu[0] + r * (KVSH * 2) + c8 * 16,
                      Khbase + (size_t)r * ED + c8 * 8);
        }
        if (tid < 16) cpasync16(sDu[0] + tid * 16, Dbase + tid * 4);
        cp_commit();
    }
    // group B: K(1)->K[1], D(1)->D[1] (if any), V(0)->V[0]
    {
        if (nkt > 1) {
            #pragma unroll
            for (int it = 0; it < 4; ++it) {
                int r = rlo8 + it * 16;
                cpasync16(sKu[1] + r * (KVSH * 2) + c8 * 16,
                          Khbase + (size_t)(BN + r) * ED + c8 * 8);
            }
            if (tid < 16) cpasync16(sDu[1] + tid * 16, Dbase + BN + tid * 4);
        }
        #pragma unroll
        for (int it = 0; it < 4; ++it) {
            int r = rlo8 + it * 16;
            cpasync16(sVu[0] + r * (KVSH * 2) + c8 * 16,
                      Vtbase + (size_t)r * LQ + c8 * 8);
        }
        cp_commit();
    }
    cp_wait1();          // group A landed
    __syncthreads();

    // ---- Q fragments as half2 (one-time) ----
    uint32_t qh[4][4];
    {
        const float* qb = sQ + (wrow + g) * QSTR;
        #pragma unroll
        for (int kk = 0; kk < 4; ++kk) {
            float2 x0 = *(const float2*)(qb + 16 * kk + 2 * t4);
            float2 x1 = *(const float2*)(qb + 8 * QSTR + 16 * kk + 2 * t4);
            float2 x2 = *(const float2*)(qb + 16 * kk + 8 + 2 * t4);
            float2 x3 = *(const float2*)(qb + 8 * QSTR + 16 * kk + 8 + 2 * t4);
            qh[kk][0] = pack_h2(x0.x, x0.y);
            qh[kk][1] = pack_h2(x1.x, x1.y);
            qh[kk][2] = pack_h2(x2.x, x2.y);
            qh[kk][3] = pack_h2(x3.x, x3.y);
        }
    }

    float m_i[2] = {-1e30f, -1e30f};
    float l_i[2] = {0.f, 0.f};
    float Oacc[8][4];
    #pragma unroll
    for (int j = 0; j < 8; ++j)
        #pragma unroll
        for (int i = 0; i < 4; ++i) Oacc[j][i] = 0.f;

    float Sacc[8][4];

    // ---- Sacc(0) = QK(0) + mask(0) (in-prologue peel) ----
    {
        #pragma unroll
        for (int j = 0; j < 8; ++j)
            #pragma unroll
            for (int i = 0; i < 4; ++i) Sacc[j][i] = 0.f;
        const __half* sKc = sKh[0];
        #pragma unroll
        for (int kk = 0; kk < 4; ++kk) {
            #pragma unroll
            for (int j = 0; j < 8; ++j) {
                uint2 bv = *(const uint2*)(sKc + (8 * j + g) * KVSH + 16 * kk + 4 * t4);
                mma_f16(Sacc[j], qh[kk], bv.x, bv.y);
            }
        }
        const float* sDc = sD[0];
        const int cb = 2 * t4;
        #pragma unroll
        for (int j = 0; j < 8; ++j) {
            int c0 = cb + 8 * j;
            float2 d = *(const float2*)(sDc + 8 * j + 2 * t4);
            float dx = d.x * scale, dy = d.y * scale;
            float s0 = Sacc[j][0] * ts + dx;
            float s1 = Sacc[j][1] * ts + dy;
            float s2 = Sacc[j][2] * ts + dx;
            float s3 = Sacc[j][3] * ts + dy;
            if (c0     > row0) s0 = -1e30f;
            if (c0 + 1 > row0) s1 = -1e30f;
            if (c0     > row1) s2 = -1e30f;
            if (c0 + 1 > row1) s3 = -1e30f;
            Sacc[j][0] = s0; Sacc[j][1] = s1; Sacc[j][2] = s2; Sacc[j][3] = s3;
        }
    }

    for (int kt = 0; kt < nkt; ++kt) {
        // ---- 1. softmax(kt): Sacc -> ph; update m,l; scale Oacc ----
        uint32_t ph[8][2];
        #pragma unroll
        for (int hh = 0; hh < 2; ++hh) {
            float mx = -1e30f;
            #pragma unroll
            for (int j = 0; j < 8; ++j)
                mx = fmaxf(mx, fmaxf(Sacc[j][2 * hh], Sacc[j][2 * hh + 1]));
            mx = fmaxf(mx, __shfl_xor_sync(0xffffffffu, mx, 1));
            mx = fmaxf(mx, __shfl_xor_sync(0xffffffffu, mx, 2));
            float mnew  = fmaxf(m_i[hh], mx);
            float alpha = __expf(m_i[hh] - mnew);
            float psum = 0.f;
            #pragma unroll
            for (int j = 0; j < 8; ++j) {
                float p0 = __expf(Sacc[j][2 * hh]     - mnew);
                float p1 = __expf(Sacc[j][2 * hh + 1] - mnew);
                psum += p0 + p1;
                ph[j][hh] = pack_h2(p0, p1);
            }
            psum += __shfl_xor_sync(0xffffffffu, psum, 1);
            psum += __shfl_xor_sync(0xffffffffu, psum, 2);
            l_i[hh] = l_i[hh] * alpha + psum;
            m_i[hh] = mnew;
            #pragma unroll
            for (int j = 0; j < 8; ++j) {
                Oacc[j][2 * hh]     *= alpha;
                Oacc[j][2 * hh + 1] *= alpha;
            }
        }

        // ---- 2. wait for (kt+1) K/D and (kt) V; make visible ----
        cp_wait0();
        __syncthreads();

        // ---- 3. prefetch: K,D(kt+2) -> [kt&1]; V(kt+1) -> [1-(kt&1)] ----
        {
            bool any = false;
            if (kt + 2 < nkt) {
                const int kr0 = (kt + 2) * BN;
                #pragma unroll
                for (int it = 0; it < 4; ++it) {
                    int r = rlo8 + it * 16;
                    cpasync16(sKu[kt & 1] + r * (KVSH * 2) + c8 * 16,
                              Khbase + (size_t)(kr0 + r) * ED + c8 * 8);
                }
                if (tid < 16) cpasync16(sDu[kt & 1] + tid * 16, Dbase + kr0 + tid * 4);
                any = true;
            }
            if (kt + 1 < nkt) {
                const int vr0 = (kt + 1) * BN;
                #pragma unroll
                for (int it = 0; it < 4; ++it) {
                    int r = rlo8 + it * 16;
                    cpasync16(sVu[1 - (kt & 1)] + r * (KVSH * 2) + c8 * 16,
                              Vtbase + (size_t)r * LQ + vr0 + c8 * 8);
                }
                any = true;
            }
            if (any) cp_commit();
        }

        // ---- 4. MMA block: QK(kt+1) (into Sacc) ∥ PV(kt) (into Oacc) ----
        if (kt + 1 < nkt) {
            #pragma unroll
            for (int j = 0; j < 8; ++j)
                #pragma unroll
                for (int i = 0; i < 4; ++i) Sacc[j][i] = 0.f;
            const __half* sKc = sKh[(kt + 1) & 1];
            const __half* sVc = sVh[kt & 1];
            #pragma unroll
            for (int kk = 0; kk < 4; ++kk) {
                uint32_t A[4] = { ph[2 * kk][0], ph[2 * kk][1],
                                  ph[2 * kk + 1][0], ph[2 * kk + 1][1] };
                #pragma unroll
                for (int j = 0; j < 8; ++j) {
                    uint2 bk = *(const uint2*)(sKc + (8 * j + g) * KVSH + 16 * kk + 4 * t4);
                    mma_f16(Sacc[j], qh[kk], bk.x, bk.y);
                    uint2 bv = *(const uint2*)(sVc + (8 * j + g) * KVSH + 16 * kk + 4 * t4);
                    mma_f16(Oacc[j], A, bv.x, bv.y);
                }
            }
            // mask + delta for tile kt+1
            const float* sDc = sD[(kt + 1) & 1];
            const int cb = (kt + 1) * BN + 2 * t4;
            #pragma unroll
            for (int j = 0; j < 8; ++j) {
                int c0 = cb + 8 * j;
                float2 d = *(const float2*)(sDc + 8 * j + 2 * t4);
                float dx = d.x * scale, dy = d.y * scale;
                float s0 = Sacc[j][0] * ts + dx;
                float s1 = Sacc[j][1] * ts + dy;
                float s2 = Sacc[j][2] * ts + dx;
                float s3 = Sacc[j][3] * ts + dy;
                if (c0     > row0) s0 = -1e30f;
                if (c0 + 1 > row0) s1 = -1e30f;
                if (c0     > row1) s2 = -1e30f;
                if (c0 + 1 > row1) s3 = -1e30f;
                Sacc[j][0] = s0; Sacc[j][1] = s1; Sacc[j][2] = s2; Sacc[j][3] = s3;
            }
        } else {
            // last tile: PV only
            const __half* sVc = sVh[kt & 1];
            #pragma unroll
            for (int kk = 0; kk < 4; ++kk) {
                uint32_t A[4] = { ph[2 * kk][0], ph[2 * kk][1],
                                  ph[2 * kk + 1][0], ph[2 * kk + 1][1] };
                #pragma unroll
                for (int j = 0; j < 8; ++j) {
                    uint2 bv = *(const uint2*)(sVc + (8 * j + g) * KVSH + 16 * kk + 4 * t4);
                    mma_f16(Oacc[j], A, bv.x, bv.y);
                }
            }
        }
    }

    // ---- finalize & write ----
    {
        float inv0 = 1.0f / l_i[0];
        float inv1 = 1.0f / l_i[1];
        float* o0 = Og + (((size_t)(b * LQ + row0)) * HH + h) * ED;
        float* o1 = Og + (((size_t)(b * LQ + row1)) * HH + h) * ED;
        #pragma unroll
        for (int j = 0; j < 8; ++j) {
            int e = 8 * j + 2 * t4;
            *(float2*)(o0 + e) = make_float2(Oacc[j][0] * inv0, Oacc[j][1] * inv0);
            *(float2*)(o1 + e) = make_float2(Oacc[j][2] * inv1, Oacc[j][3] * inv1);
        }
    }
}

extern "C" void kernel_launch(void* const* d_in, const int* in_sizes, int n_in,
                              void* d_out, int out_size)
{
    const float* Q     = (const float*)d_in[0];
    const float* K     = (const float*)d_in[1];
    const float* V     = (const float*)d_in[2];
    const float* tau   = (const float*)d_in[3];
    const float* delta = (const float*)d_in[4];
    float* out = (float*)d_out;

    cudaFuncSetAttribute(dsattn_tc,
                         cudaFuncAttributeMaxDynamicSharedMemorySize, SMEM_BYTES);

    dim3 pgrid(LQ / 64, HH, 2);
    prep_kernel<<<pgrid, 256>>>(K, V);

    dim3 grid(LQ / BM, HH, 2);   // 512 CTAs
    dsattn_tc<<<grid, NTHREADS, SMEM_BYTES>>>(Q, tau, delta, out);
}

// round 17
// speedup vs baseline: 1.2670x; 1.2670x over previous
#include <cuda_runtime.h>
#include <cuda_fp16.h>
#include <cstdint>

// DSAttention flash attention, all-fp16 MMA (fp32 accum). R15 serial schedule
// (proven fastest) + instruction-count cuts:
//  - B-fragment smem layout [t4][kk][i] -> one LDS.128 per kk-PAIR (halves LDS count)
//  - delta prescaled by 1/8 in prep
//  - causal mask applied only on the diagonal tile (block-uniform branch)
// Double-buffered cp.async (K,V,delta), one barrier per tile, 3 CTAs/SM.

#define LQ 2048
#define HH 8
#define BM 64
#define BN 64
#define ED 64
#define NTHREADS 128
#define KVSH 72                  // halves per row (144 B)
#define KVB  (64 * KVSH * 2)     // 9216 B per tile buffer
#define QSTR 68                  // floats per Q-stage row

#define OFFB_K0 0
#define OFFB_K1 (KVB)
#define OFFB_V0 (2 * KVB)
#define OFFB_V1 (3 * KVB)
#define OFFB_D0 (4 * KVB)
#define OFFB_D1 (4 * KVB + 256)
#define OFFB_Q  (4 * KVB + 512)
#define SMEM_BYTES (OFFB_Q + 64 * QSTR * 4)   // 54784 B -> 3 CTAs/SM

__device__ __half g_Kh[2 * 8 * 2048 * 64];    // 4 MB: fp16 K, [bh][s][e packed]
__device__ __half g_Vth[2 * 8 * 64 * 2048];   // 4 MB: fp16 V, [bh][e][s packed]
__device__ float  g_Ds[2 * 2048];             // delta * 0.125

__device__ __forceinline__ uint32_t pack_h2(float a, float b) {
    __half2 h = __floats2half2_rn(a, b);
    return *(uint32_t*)&h;
}
__device__ __forceinline__ void cpasync16(uint32_t dst, const void* src) {
    asm volatile("cp.async.cg.shared.global [%0], [%1], 16;" :: "r"(dst), "l"(src));
}
__device__ __forceinline__ void cp_commit() {
    asm volatile("cp.async.commit_group;" ::: "memory");
}
__device__ __forceinline__ void cp_wait0() {
    asm volatile("cp.async.wait_group 0;" ::: "memory");
}
__device__ __forceinline__ void mma_f16(float* d, const uint32_t* a,
                                        uint32_t b0, uint32_t b1) {
    asm volatile(
        "mma.sync.aligned.m16n8k16.row.col.f32.f16.f16.f32 "
        "{%0,%1,%2,%3}, {%4,%5,%6,%7}, {%8,%9}, {%0,%1,%2,%3};"
        : "+f"(d[0]), "+f"(d[1]), "+f"(d[2]), "+f"(d[3])
        : "r"(a[0]), "r"(a[1]), "r"(a[2]), "r"(a[3]), "r"(b0), "r"(b1));
}

// ---------------- prep ----------------
// Packed row layout (64 halves): offset q = t4*16 + kk*4 + i holds logical
// element kk*16 + 2*t4 + (i&1) + 8*((i>>1)&1)  -> thread (g,t4) reads ONE
// uint4 at t4*16 + kp*8 for the kk-pair {2kp, 2kp+1}.
__global__ __launch_bounds__(256)
void prep_kernel(const float* __restrict__ Kg, const float* __restrict__ Vg,
                 const float* __restrict__ Dg)
{
    const int stile = blockIdx.x;
    const int h     = blockIdx.y;
    const int b     = blockIdx.z;
    const int tid   = threadIdx.x;
    const int bh    = b * HH + h;
    const int s0    = stile * 64;

    __shared__ float tile[64][65];

    if (h == 0 && tid < 64)
        g_Ds[b * LQ + s0 + tid] = Dg[b * LQ + s0 + tid] * 0.125f;

    // ---- K phase: load rows, gather-pack ----
    #pragma unroll
    for (int it = 0; it < 4; ++it) {
        int u  = tid + it * 256;
        int r  = u >> 4;
        int c4 = u & 15;
        float4 v = *(const float4*)(Kg + ((size_t)(b * LQ + s0 + r) * HH + h) * ED + 4 * c4);
        tile[r][4 * c4 + 0] = v.x;
        tile[r][4 * c4 + 1] = v.y;
        tile[r][4 * c4 + 2] = v.z;
        tile[r][4 * c4 + 3] = v.w;
    }
    __syncthreads();
    {
        int r  = tid >> 2;
        int t4 = tid & 3;
        __half out16[16];
        #pragma unroll
        for (int kk = 0; kk < 4; ++kk)
            #pragma unroll
            for (int i = 0; i < 4; ++i) {
                int lg = kk * 16 + 2 * t4 + (i & 1) + 8 * ((i >> 1) & 1);
                out16[kk * 4 + i] = __float2half_rn(tile[r][lg]);
            }
        __half* dst = g_Kh + ((size_t)bh * LQ + s0 + r) * ED + t4 * 16;
        *(uint4*)(dst)     = *(uint4*)(out16);
        *(uint4*)(dst + 8) = *(uint4*)(out16 + 8);
    }
    __syncthreads();

    // ---- V phase: load rows, gather-pack transposed ----
    #pragma unroll
    for (int it = 0; it < 4; ++it) {
        int u  = tid + it * 256;
        int r  = u >> 4;
        int c4 = u & 15;
        float4 v = *(const float4*)(Vg + ((size_t)(b * LQ + s0 + r) * HH + h) * ED + 4 * c4);
        tile[r][4 * c4 + 0] = v.x;
        tile[r][4 * c4 + 1] = v.y;
        tile[r][4 * c4 + 2] = v.z;
        tile[r][4 * c4 + 3] = v.w;
    }
    __syncthreads();
    {
        int e  = tid >> 2;
        int t4 = tid & 3;
        __half out16[16];
        #pragma unroll
        for (int kk = 0; kk < 4; ++kk)
            #pragma unroll
            for (int i = 0; i < 4; ++i) {
                int ls = kk * 16 + 2 * t4 + (i & 1) + 8 * ((i >> 1) & 1);
                out16[kk * 4 + i] = __float2half_rn(tile[ls][e]);
            }
        __half* dst = g_Vth + ((size_t)bh * ED + e) * LQ + s0 + t4 * 16;
        *(uint4*)(dst)     = *(uint4*)(out16);
        *(uint4*)(dst + 8) = *(uint4*)(out16 + 8);
    }
}

// ---------------- main ----------------
__global__ __launch_bounds__(NTHREADS, 3)
void dsattn_tc(const float* __restrict__ Qg, const float* __restrict__ Taug,
               float* __restrict__ Og)
{
    const int mtile = (int)gridDim.x - 1 - (int)blockIdx.x;   // heavy first
    const int h     = blockIdx.y;
    const int b     = blockIdx.z;
    const int bh    = b * HH + h;

    const int tid  = threadIdx.x;
    const int wid  = tid >> 5;
    const int lane = tid & 31;
    const int g    = lane >> 2;
    const int t4   = lane & 3;

    extern __shared__ char smemc[];
    __half* sKh[2] = { (__half*)(smemc + OFFB_K0), (__half*)(smemc + OFFB_K1) };
    __half* sVh[2] = { (__half*)(smemc + OFFB_V0), (__half*)(smemc + OFFB_V1) };
    float*  sD [2] = { (float*)(smemc + OFFB_D0),  (float*)(smemc + OFFB_D1) };
    float*  sQ     = (float*)(smemc + OFFB_Q);

    const uint32_t su = (uint32_t)__cvta_generic_to_shared(smemc);
    const uint32_t sKu[2] = { su + OFFB_K0, su + OFFB_K1 };
    const uint32_t sVu[2] = { su + OFFB_V0, su + OFFB_V1 };
    const uint32_t sDu[2] = { su + OFFB_D0, su + OFFB_D1 };
    const uint32_t sQu    = su + OFFB_Q;

    const float ts = Taug[b] * 0.125f;
    const int wrow = wid * 16;

    const float*  Qbase  = Qg + ((size_t)(b * LQ) * HH + h) * ED;
    const __half* Khbase = g_Kh + (size_t)bh * LQ * ED;
    const __half* Vtbase = g_Vth + (size_t)bh * ED * LQ;
    const float*  Dbase  = g_Ds + b * LQ;

    const int nkt = mtile + 1;
    const int rlo8 = tid >> 3, c8 = tid & 7;   // KV loader coords (128 B rows)

    // ---- prologue: Q stage + K0 + V0 + D0, one wait ----
    {
        const int q0 = mtile * BM;
        const int r_lo = tid >> 4, c4 = tid & 15;
        #pragma unroll
        for (int it = 0; it < 8; ++it) {
            int r = r_lo + it * 8;
            cpasync16(sQu + (r * QSTR + c4 * 4) * 4,
                      Qbase + (size_t)(q0 + r) * (HH * ED) + c4 * 4);
        }
        #pragma unroll
        for (int it = 0; it < 4; ++it) {
            int r = rlo8 + it * 16;
            cpasync16(sKu[0] + r * (KVSH * 2) + c8 * 16,
                      Khbase + (size_t)r * ED + c8 * 8);
            cpasync16(sVu[0] + r * (KVSH * 2) + c8 * 16,
                      Vtbase + (size_t)r * LQ + c8 * 8);
        }
        if (tid < 16) cpasync16(sDu[0] + tid * 16, Dbase + tid * 4);
        cp_commit();
        cp_wait0();
    }
    __syncthreads();

    // ---- Q fragments as half2 (one-time) ----
    uint32_t qh[4][4];
    {
        const float* qb = sQ + (wrow + g) * QSTR;
        #pragma unroll
        for (int kk = 0; kk < 4; ++kk) {
            float2 x0 = *(const float2*)(qb + 16 * kk + 2 * t4);
            float2 x1 = *(const float2*)(qb + 8 * QSTR + 16 * kk + 2 * t4);
            float2 x2 = *(const float2*)(qb + 16 * kk + 8 + 2 * t4);
            float2 x3 = *(const float2*)(qb + 8 * QSTR + 16 * kk + 8 + 2 * t4);
            qh[kk][0] = pack_h2(x0.x, x0.y);
            qh[kk][1] = pack_h2(x1.x, x1.y);
            qh[kk][2] = pack_h2(x2.x, x2.y);
            qh[kk][3] = pack_h2(x3.x, x3.y);
        }
    }

    float m_i[2] = {-1e30f, -1e30f};
    float l_i[2] = {0.f, 0.f};
    float Oacc[8][4];
    #pragma unroll
    for (int j = 0; j < 8; ++j)
        #pragma unroll
        for (int i = 0; i < 4; ++i) Oacc[j][i] = 0.f;

    const int row0 = mtile * BM + wrow + g;
    const int row1 = row0 + 8;

    for (int kt = 0; kt < nkt; ++kt) {
        cp_wait0();
        __syncthreads();   // tile kt visible; buffers [1-cur] free

        const int cur = kt & 1;

        // ---- prefetch tile kt+1 ----
        if (kt + 1 < nkt) {
            const int kr0 = (kt + 1) * BN;
            #pragma unroll
            for (int it = 0; it < 4; ++it) {
                int r = rlo8 + it * 16;
                cpasync16(sKu[1 - cur] + r * (KVSH * 2) + c8 * 16,
                          Khbase + (size_t)(kr0 + r) * ED + c8 * 8);
                cpasync16(sVu[1 - cur] + r * (KVSH * 2) + c8 * 16,
                          Vtbase + (size_t)r * LQ + kr0 + c8 * 8);
            }
            if (tid < 16) cpasync16(sDu[1 - cur] + tid * 16, Dbase + kr0 + tid * 4);
            cp_commit();
        }

        // ---- S = Q @ K^T (fp16, LDS.128 B-frags) ----
        float Sacc[8][4];
        #pragma unroll
        for (int j = 0; j < 8; ++j)
            #pragma unroll
            for (int i = 0; i < 4; ++i) Sacc[j][i] = 0.f;

        const __half* sKc = sKh[cur];
        #pragma unroll
        for (int kp = 0; kp < 2; ++kp) {
            #pragma unroll
            for (int j = 0; j < 8; ++j) {
                uint4 bk = *(const uint4*)(sKc + (8 * j + g) * KVSH + t4 * 16 + kp * 8);
                mma_f16(Sacc[j], qh[2 * kp],     bk.x, bk.y);
                mma_f16(Sacc[j], qh[2 * kp + 1], bk.z, bk.w);
            }
        }

        // ---- delta (prescaled) + tau; causal mask on diagonal tile only ----
        const float* sDc = sD[cur];
        #pragma unroll
        for (int j = 0; j < 8; ++j) {
            float2 d = *(const float2*)(sDc + 8 * j + 2 * t4);
            Sacc[j][0] = Sacc[j][0] * ts + d.x;
            Sacc[j][1] = Sacc[j][1] * ts + d.y;
            Sacc[j][2] = Sacc[j][2] * ts + d.x;
            Sacc[j][3] = Sacc[j][3] * ts + d.y;
        }
        if (kt == nkt - 1) {   // block-uniform
            const int cb = kt * BN + 2 * t4;
            #pragma unroll
            for (int j = 0; j < 8; ++j) {
                int c0 = cb + 8 * j;
                if (c0     > row0) Sacc[j][0] = -1e30f;
                if (c0 + 1 > row0) Sacc[j][1] = -1e30f;
                if (c0     > row1) Sacc[j][2] = -1e30f;
                if (c0 + 1 > row1) Sacc[j][3] = -1e30f;
            }
        }

        // ---- online softmax; P packed to half2 in registers ----
        uint32_t ph[8][2];
        #pragma unroll
        for (int hh = 0; hh < 2; ++hh) {
            float mx = -1e30f;
            #pragma unroll
            for (int j = 0; j < 8; ++j)
                mx = fmaxf(mx, fmaxf(Sacc[j][2 * hh], Sacc[j][2 * hh + 1]));
            mx = fmaxf(mx, __shfl_xor_sync(0xffffffffu, mx, 1));
            mx = fmaxf(mx, __shfl_xor_sync(0xffffffffu, mx, 2));
            float mnew  = fmaxf(m_i[hh], mx);
            float alpha = __expf(m_i[hh] - mnew);
            float psum = 0.f;
            #pragma unroll
            for (int j = 0; j < 8; ++j) {
                float p0 = __expf(Sacc[j][2 * hh]     - mnew);
                float p1 = __expf(Sacc[j][2 * hh + 1] - mnew);
                psum += p0 + p1;
                ph[j][hh] = pack_h2(p0, p1);
            }
            psum += __shfl_xor_sync(0xffffffffu, psum, 1);
            psum += __shfl_xor_sync(0xffffffffu, psum, 2);
            l_i[hh] = l_i[hh] * alpha + psum;
            m_i[hh] = mnew;
            #pragma unroll
            for (int j = 0; j < 8; ++j) {
                Oacc[j][2 * hh]     *= alpha;
                Oacc[j][2 * hh + 1] *= alpha;
            }
        }

        // ---- O += P @ V (fp16, LDS.128 B-frags; A = repacked S-frags) ----
        const __half* sVc = sVh[cur];
        #pragma unroll
        for (int kp = 0; kp < 2; ++kp) {
            uint32_t A0[4] = { ph[4 * kp][0],     ph[4 * kp][1],
                               ph[4 * kp + 1][0], ph[4 * kp + 1][1] };
            uint32_t A1[4] = { ph[4 * kp + 2][0], ph[4 * kp + 2][1],
                               ph[4 * kp + 3][0], ph[4 * kp + 3][1] };
            #pragma unroll
            for (int j = 0; j < 8; ++j) {
                uint4 bv = *(const uint4*)(sVc + (8 * j + g) * KVSH + t4 * 16 + kp * 8);
                mma_f16(Oacc[j], A0, bv.x, bv.y);
                mma_f16(Oacc[j], A1, bv.z, bv.w);
            }
        }
    }

    // ---- finalize & write ----
    {
        float inv0 = 1.0f / l_i[0];
        float inv1 = 1.0f / l_i[1];
        float* o0 = Og + (((size_t)(b * LQ + row0)) * HH + h) * ED;
        float* o1 = Og + (((size_t)(b * LQ + row1)) * HH + h) * ED;
        #pragma unroll
        for (int j = 0; j < 8; ++j) {
            int e = 8 * j + 2 * t4;
            *(float2*)(o0 + e) = make_float2(Oacc[j][0] * inv0, Oacc[j][1] * inv0);
            *(float2*)(o1 + e) = make_float2(Oacc[j][2] * inv1, Oacc[j][3] * inv1);
        }
    }
}

extern "C" void kernel_launch(void* const* d_in, const int* in_sizes, int n_in,
                              void* d_out, int out_size)
{
    const float* Q     = (const float*)d_in[0];
    const float* K     = (const float*)d_in[1];
    const float* V     = (const float*)d_in[2];
    const float* tau   = (const float*)d_in[3];
    const float* delta = (const float*)d_in[4];
    float* out = (float*)d_out;

    cudaFuncSetAttribute(dsattn_tc,
                         cudaFuncAttributeMaxDynamicSharedMemorySize, SMEM_BYTES);

    dim3 pgrid(LQ / 64, HH, 2);
    prep_kernel<<<pgrid, 256>>>(K, V, delta);

    dim3 grid(LQ / BM, HH, 2);   // 512 CTAs
    dsattn_tc<<<grid, NTHREADS, SMEM_BYTES>>>(Q, tau, out);
}